// round 4
// baseline (speedup 1.0000x reference)
#include <cuda_runtime.h>
#include <cstdint>

// Problem dims
#define Bc 8
#define Tc 2048
#define Hc 64
#define Mc 32
#define Sc 20
#define Ec 3
#define INc 32
#define BTc (Bc*Tc)          // 16384
#define EPSc 1e-8f
#define LOG2E 1.4426950408889634f

// Scratch (static __device__ arrays: allocation-free per harness rules)
__device__ float g_Q[Ec*BTc*Mc];   // Q pre-scaled by log2(e)
__device__ float g_K[Ec*BTc*Mc];
__device__ float g_V[Ec*BTc*Mc];
__device__ float g_mem[BTc*Mc];    // memories [B*T, 32]

// ---------- packed f32x2 helpers ----------
__device__ __forceinline__ unsigned long long fma2(unsigned long long a,
                                                   unsigned long long b,
                                                   unsigned long long c) {
    unsigned long long d;
    asm("fma.rn.f32x2 %0, %1, %2, %3;" : "=l"(d) : "l"(a), "l"(b), "l"(c));
    return d;
}
__device__ __forceinline__ unsigned long long mul2(unsigned long long a,
                                                   unsigned long long b) {
    unsigned long long d;
    asm("mul.rn.f32x2 %0, %1, %2;" : "=l"(d) : "l"(a), "l"(b));
    return d;
}
__device__ __forceinline__ unsigned long long pack2(float x, float y) {
    unsigned long long v;
    asm("mov.b64 %0, {%1, %2};" : "=l"(v) : "f"(x), "f"(y));
    return v;
}
__device__ __forceinline__ float2 unpack2(unsigned long long v) {
    float2 f;
    asm("mov.b64 {%0, %1}, %2;" : "=f"(f.x), "=f"(f.y) : "l"(v));
    return f;
}
__device__ __forceinline__ float ex2(float x) {
    float r;
    asm("ex2.approx.f32 %0, %1;" : "=f"(r) : "f"(x));
    return r;
}

// ============================================================================
// Kernel 1: memories = softmax(x@IQ @ mem^T) @ mem     [B*T, 32]
// One thread per (b,t) row.
// ============================================================================
__global__ __launch_bounds__(128)
void k_mem(const float* __restrict__ x, const float* __restrict__ memory,
           const float* __restrict__ iq) {
    __shared__ float IQs[INc*Mc];    // 1024
    __shared__ float MEMs[Sc*Mc];    // 640
    int tid = threadIdx.x;
    for (int i = tid; i < INc*Mc; i += 128) IQs[i] = iq[i];
    for (int i = tid; i < Sc*Mc; i += 128) MEMs[i] = memory[i];
    __syncthreads();

    int row = blockIdx.x * 128 + tid;
    const float4* x4 = (const float4*)(x + (size_t)row * INc);
    float xr[INc];
    #pragma unroll
    for (int i = 0; i < 8; i++) {
        float4 v = x4[i];
        xr[4*i] = v.x; xr[4*i+1] = v.y; xr[4*i+2] = v.z; xr[4*i+3] = v.w;
    }
    float q[Mc];
    #pragma unroll
    for (int m = 0; m < Mc; m++) q[m] = 0.f;
    #pragma unroll
    for (int i = 0; i < INc; i++) {
        float xi = xr[i];
        #pragma unroll
        for (int m = 0; m < Mc; m++) q[m] = fmaf(xi, IQs[i*Mc + m], q[m]);
    }
    float lg[Sc];
    #pragma unroll
    for (int s = 0; s < Sc; s++) {
        float acc = 0.f;
        #pragma unroll
        for (int m = 0; m < Mc; m++) acc = fmaf(q[m], MEMs[s*Mc + m], acc);
        lg[s] = acc;
    }
    float mx = lg[0];
    #pragma unroll
    for (int s = 1; s < Sc; s++) mx = fmaxf(mx, lg[s]);
    float sum = 0.f;
    #pragma unroll
    for (int s = 0; s < Sc; s++) {
        lg[s] = ex2((lg[s] - mx) * LOG2E);
        sum += lg[s];
    }
    float inv = 1.0f / sum;
    #pragma unroll
    for (int m = 0; m < Mc; m++) {
        float acc = 0.f;
        #pragma unroll
        for (int s = 0; s < Sc; s++) acc = fmaf(lg[s], MEMs[s*Mc + m], acc);
        g_mem[(size_t)row*Mc + m] = acc * inv;
    }
}

// ============================================================================
// Kernel 2: QKV projections per expert. hidden[E,B*T,64] @ W[e][64,32].
// One warp per row; lane = output column m. Q pre-scaled by log2(e).
// ============================================================================
__global__ __launch_bounds__(256)
void k_qkv(const float* __restrict__ hidden, const float* __restrict__ Wq,
           const float* __restrict__ Wk, const float* __restrict__ Wv) {
    __shared__ float Ws[3*Hc*Mc];   // 6144 floats
    int e = blockIdx.y;
    int tid = threadIdx.x;
    {
        const float4* wq4 = (const float4*)(Wq + (size_t)e*Hc*Mc);
        const float4* wk4 = (const float4*)(Wk + (size_t)e*Hc*Mc);
        const float4* wv4 = (const float4*)(Wv + (size_t)e*Hc*Mc);
        float4* s0 = (float4*)Ws;
        float4* s1 = (float4*)(Ws + Hc*Mc);
        float4* s2 = (float4*)(Ws + 2*Hc*Mc);
        for (int i = tid; i < Hc*Mc/4; i += 256) {
            s0[i] = wq4[i]; s1[i] = wk4[i]; s2[i] = wv4[i];
        }
    }
    __syncthreads();

    int warp = tid >> 5, lane = tid & 31;
    int rbase = blockIdx.x * 256 + warp * 32;
    for (int i = 0; i < 32; ++i) {
        int row = rbase + i;
        size_t hoff = ((size_t)e*BTc + row) * Hc;
        float2 h2 = ((const float2*)(hidden + hoff))[lane];
        float qa = 0.f, ka = 0.f, va = 0.f;
        #pragma unroll
        for (int h = 0; h < Hc; ++h) {
            float hv = __shfl_sync(0xffffffffu, (h & 1) ? h2.y : h2.x, h >> 1);
            qa = fmaf(hv, Ws[h*Mc + lane], qa);
            ka = fmaf(hv, Ws[Hc*Mc + h*Mc + lane], ka);
            va = fmaf(hv, Ws[2*Hc*Mc + h*Mc + lane], va);
        }
        size_t o = ((size_t)e*BTc + row) * Mc + lane;
        g_Q[o] = qa * LOG2E;
        g_K[o] = ka;
        g_V[o] = va;
    }
}

// ============================================================================
// Kernel 3: flash attention (online softmax, fp32 via packed f32x2 FMA)
// fused with cosine epilogue. One thread per query row; BK=32 key tile in
// smem; key tile processed in two 16-key chunks.
// grid (T/128, B, E), block 128.
// ============================================================================
#define BK 32
__global__ __launch_bounds__(128)
void k_attn(float* __restrict__ out) {
    __shared__ __align__(16) float Ks[BK*Mc];
    __shared__ __align__(16) float Vs[BK*Mc];

    int tid = threadIdx.x;
    int t = blockIdx.x * 128 + tid;
    int b = blockIdx.y, e = blockIdx.z;
    int eb = e * Bc + b;

    // load query row (already log2e-scaled)
    unsigned long long qp[16];
    {
        const ulonglong2* q2 = (const ulonglong2*)(g_Q + ((size_t)eb*Tc + t) * Mc);
        #pragma unroll
        for (int i = 0; i < 8; i++) {
            ulonglong2 v = q2[i];
            qp[2*i] = v.x; qp[2*i+1] = v.y;
        }
    }
    unsigned long long op[16];
    #pragma unroll
    for (int i = 0; i < 16; i++) op[i] = 0ull;
    float mrun = -1e30f, lrun = 0.f;

    const float4* K4 = (const float4*)g_K;
    const float4* V4 = (const float4*)g_V;
    size_t base4 = (size_t)eb * (Tc*Mc/4);

    // prefetch tile 0 into registers
    float4 ka = K4[base4 + tid], kb = K4[base4 + tid + 128];
    float4 va = V4[base4 + tid], vb = V4[base4 + tid + 128];

    const ulonglong2* Ks2 = (const ulonglong2*)Ks;
    const ulonglong2* Vs2 = (const ulonglong2*)Vs;

    const int nt = Tc / BK;  // 64
    for (int tile = 0; tile < nt; ++tile) {
        __syncthreads();                       // previous compute done
        ((float4*)Ks)[tid] = ka; ((float4*)Ks)[tid+128] = kb;
        ((float4*)Vs)[tid] = va; ((float4*)Vs)[tid+128] = vb;
        __syncthreads();                       // tile visible
        if (tile + 1 < nt) {
            size_t nb = base4 + (size_t)(tile+1) * (BK*Mc/4);
            ka = K4[nb + tid]; kb = K4[nb + tid + 128];
            va = V4[nb + tid]; vb = V4[nb + tid + 128];
        }

        #pragma unroll
        for (int c = 0; c < 2; ++c) {
            const int j0 = c * 16;
            // ---- S = q . K for 16 keys (packed pairs over m) ----
            unsigned long long sp[16];
            #pragma unroll
            for (int j = 0; j < 16; j++) sp[j] = 0ull;
            #pragma unroll
            for (int mp = 0; mp < 8; ++mp) {
                unsigned long long qa2 = qp[2*mp], qb2 = qp[2*mp+1];
                #pragma unroll
                for (int j = 0; j < 16; ++j) {
                    ulonglong2 k2 = Ks2[(j0 + j)*8 + mp];
                    sp[j] = fma2(qa2, k2.x, sp[j]);
                    sp[j] = fma2(qb2, k2.y, sp[j]);
                }
            }
            float s[16];
            float cmax = -1e30f;
            #pragma unroll
            for (int j = 0; j < 16; ++j) {
                float2 f = unpack2(sp[j]);
                s[j] = f.x + f.y;
                cmax = fmaxf(cmax, s[j]);
            }
            // ---- online softmax rescale ----
            float newm = fmaxf(mrun, cmax);
            float sc = ex2(mrun - newm);   // 1.0 when unchanged
            mrun = newm;
            lrun *= sc;
            unsigned long long sc2 = pack2(sc, sc);
            #pragma unroll
            for (int mp = 0; mp < 16; ++mp) op[mp] = mul2(op[mp], sc2);
            // ---- O += p * V ----
            #pragma unroll
            for (int j = 0; j < 16; ++j) {
                float p = ex2(s[j] - mrun);
                lrun += p;
                unsigned long long p2 = pack2(p, p);
                #pragma unroll
                for (int mp = 0; mp < 8; ++mp) {
                    ulonglong2 v2 = Vs2[(j0 + j)*8 + mp];
                    op[2*mp]   = fma2(p2, v2.x, op[2*mp]);
                    op[2*mp+1] = fma2(p2, v2.y, op[2*mp+1]);
                }
            }
        }
    }

    // ---- finalize: out = o / l ; cosine with memories ----
    float inv_l = 1.0f / lrun;
    float on[Mc];
    #pragma unroll
    for (int i = 0; i < 16; ++i) {
        float2 f = unpack2(op[i]);
        on[2*i] = f.x * inv_l;
        on[2*i+1] = f.y * inv_l;
    }
    float dot = 0.f, no2 = 0.f, nm2 = 0.f;
    const float4* mem4 = (const float4*)(g_mem + ((size_t)b*Tc + t) * Mc);
    #pragma unroll
    for (int i = 0; i < 8; ++i) {
        float4 mm = mem4[i];
        float o0 = on[4*i], o1 = on[4*i+1], o2 = on[4*i+2], o3 = on[4*i+3];
        dot += mm.x*o0 + mm.y*o1 + mm.z*o2 + mm.w*o3;
        nm2 += mm.x*mm.x + mm.y*mm.y + mm.z*mm.z + mm.w*mm.w;
        no2 += o0*o0 + o1*o1 + o2*o2 + o3*o3;
    }
    float cosv = dot / (fmaxf(sqrtf(nm2), EPSc) * fmaxf(sqrtf(no2), EPSc));
    out[((size_t)b*Tc + t) * Ec + e] = cosv;
}

// ============================================================================
extern "C" void kernel_launch(void* const* d_in, const int* in_sizes, int n_in,
                              void* d_out, int out_size) {
    (void)in_sizes; (void)n_in; (void)out_size;
    const float* x      = (const float*)d_in[0];
    const float* hidden = (const float*)d_in[1];
    const float* memory = (const float*)d_in[2];
    const float* Wq     = (const float*)d_in[3];
    const float* Wk     = (const float*)d_in[4];
    const float* Wv     = (const float*)d_in[5];
    const float* iq     = (const float*)d_in[6];
    float* out = (float*)d_out;

    k_mem<<<BTc/128, 128>>>(x, memory, iq);
    k_qkv<<<dim3(BTc/256, Ec), 256>>>(hidden, Wq, Wk, Wv);
    k_attn<<<dim3(Tc/128, Bc, Ec), 128>>>(out);
}

// round 5
// speedup vs baseline: 1.0226x; 1.0226x over previous
#include <cuda_runtime.h>
#include <cstdint>

typedef unsigned long long ull;

// Problem dims
#define Bc 8
#define Tc 2048
#define Hc 64
#define Mc 32
#define Sc 20
#define Ec 3
#define INc 32
#define BTc (Bc*Tc)          // 16384
#define EBT (Ec*BTc)         // 49152
#define EPSc 1e-8f
#define LOG2E 1.4426950408889634f

// split-K config for attention
#define KQS 4                // key splits
#define KEYS (Tc/KQS)        // 512 keys per block
#define NT (KEYS/32)         // 16 tiles of 32 keys

// Scratch (static __device__ arrays: allocation-free per harness rules)
__device__ float g_Q[Ec*BTc*Mc];     // Q pre-scaled by log2(e)
__device__ float g_K[Ec*BTc*Mc];
__device__ float g_V[Ec*BTc*Mc];
__device__ float g_mem[BTc*Mc];      // memories [B*T, 32]
__device__ float g_pO[KQS*EBT*Mc];   // unnormalized partial O
__device__ float g_pm[KQS*EBT];      // partial running max (log2 domain)
__device__ float g_pl[KQS*EBT];      // partial softmax denom

// ---------- packed f32x2 helpers ----------
__device__ __forceinline__ ull fma2(ull a, ull b, ull c) {
    ull d;
    asm("fma.rn.f32x2 %0, %1, %2, %3;" : "=l"(d) : "l"(a), "l"(b), "l"(c));
    return d;
}
__device__ __forceinline__ ull mul2(ull a, ull b) {
    ull d;
    asm("mul.rn.f32x2 %0, %1, %2;" : "=l"(d) : "l"(a), "l"(b));
    return d;
}
__device__ __forceinline__ ull pack2(float x, float y) {
    ull v;
    asm("mov.b64 %0, {%1, %2};" : "=l"(v) : "f"(x), "f"(y));
    return v;
}
__device__ __forceinline__ float2 unpack2(ull v) {
    float2 f;
    asm("mov.b64 {%0, %1}, %2;" : "=f"(f.x), "=f"(f.y) : "l"(v));
    return f;
}
__device__ __forceinline__ float ex2(float x) {
    float r;
    asm("ex2.approx.f32 %0, %1;" : "=f"(r) : "f"(x));
    return r;
}
// ---------- cp.async helpers ----------
__device__ __forceinline__ unsigned smem_u32(const void* p) {
    return (unsigned)__cvta_generic_to_shared(p);
}
__device__ __forceinline__ void cp16(unsigned dst, const void* src) {
    asm volatile("cp.async.cg.shared.global [%0], [%1], 16;"
                 :: "r"(dst), "l"(src));
}
__device__ __forceinline__ void cp_commit() {
    asm volatile("cp.async.commit_group;");
}
template <int N>
__device__ __forceinline__ void cp_wait() {
    asm volatile("cp.async.wait_group %0;" :: "n"(N));
}

// ============================================================================
// Kernel 1: memories = softmax(x@IQ @ mem^T) @ mem     [B*T, 32]
// One thread per (b,t) row; x streamed (no 32-reg staging -> no spills).
// ============================================================================
__global__ __launch_bounds__(128)
void k_mem(const float* __restrict__ x, const float* __restrict__ memory,
           const float* __restrict__ iq) {
    __shared__ float IQs[INc*Mc];    // 1024
    __shared__ float MEMs[Sc*Mc];    // 640
    int tid = threadIdx.x;
    for (int i = tid; i < INc*Mc; i += 128) IQs[i] = iq[i];
    for (int i = tid; i < Sc*Mc; i += 128) MEMs[i] = memory[i];
    __syncthreads();

    int row = blockIdx.x * 128 + tid;
    const float4* x4 = (const float4*)(x + (size_t)row * INc);

    float q[Mc];
    #pragma unroll
    for (int m = 0; m < Mc; m++) q[m] = 0.f;
    #pragma unroll
    for (int i4 = 0; i4 < 8; i4++) {
        float4 v = x4[i4];
        int i = i4 * 4;
        #pragma unroll
        for (int m = 0; m < Mc; m++) q[m] = fmaf(v.x, IQs[(i+0)*Mc + m], q[m]);
        #pragma unroll
        for (int m = 0; m < Mc; m++) q[m] = fmaf(v.y, IQs[(i+1)*Mc + m], q[m]);
        #pragma unroll
        for (int m = 0; m < Mc; m++) q[m] = fmaf(v.z, IQs[(i+2)*Mc + m], q[m]);
        #pragma unroll
        for (int m = 0; m < Mc; m++) q[m] = fmaf(v.w, IQs[(i+3)*Mc + m], q[m]);
    }
    float lg[Sc];
    #pragma unroll
    for (int s = 0; s < Sc; s++) {
        float acc = 0.f;
        #pragma unroll
        for (int m = 0; m < Mc; m++) acc = fmaf(q[m], MEMs[s*Mc + m], acc);
        lg[s] = acc;
    }
    float mx = lg[0];
    #pragma unroll
    for (int s = 1; s < Sc; s++) mx = fmaxf(mx, lg[s]);
    float sum = 0.f;
    #pragma unroll
    for (int s = 0; s < Sc; s++) {
        lg[s] = ex2((lg[s] - mx) * LOG2E);
        sum += lg[s];
    }
    float inv = 1.0f / sum;
    #pragma unroll
    for (int m = 0; m < Mc; m++) {
        float acc = 0.f;
        #pragma unroll
        for (int s = 0; s < Sc; s++) acc = fmaf(lg[s], MEMs[s*Mc + m], acc);
        g_mem[(size_t)row*Mc + m] = acc * inv;
    }
}

// ============================================================================
// Kernel 2: QKV projections per expert. hidden[E,B*T,64] @ W[e][64,32].
// One warp per 32 rows; lane = output column m. Q pre-scaled by log2(e).
// ============================================================================
__global__ __launch_bounds__(256)
void k_qkv(const float* __restrict__ hidden, const float* __restrict__ Wq,
           const float* __restrict__ Wk, const float* __restrict__ Wv) {
    __shared__ float Ws[3*Hc*Mc];   // 6144 floats
    int e = blockIdx.y;
    int tid = threadIdx.x;
    {
        const float4* wq4 = (const float4*)(Wq + (size_t)e*Hc*Mc);
        const float4* wk4 = (const float4*)(Wk + (size_t)e*Hc*Mc);
        const float4* wv4 = (const float4*)(Wv + (size_t)e*Hc*Mc);
        float4* s0 = (float4*)Ws;
        float4* s1 = (float4*)(Ws + Hc*Mc);
        float4* s2 = (float4*)(Ws + 2*Hc*Mc);
        for (int i = tid; i < Hc*Mc/4; i += 256) {
            s0[i] = wq4[i]; s1[i] = wk4[i]; s2[i] = wv4[i];
        }
    }
    __syncthreads();

    int warp = tid >> 5, lane = tid & 31;
    int rbase = blockIdx.x * 256 + warp * 32;
    for (int i = 0; i < 32; ++i) {
        int row = rbase + i;
        size_t hoff = ((size_t)e*BTc + row) * Hc;
        float2 h2 = ((const float2*)(hidden + hoff))[lane];
        float qa = 0.f, ka = 0.f, va = 0.f;
        #pragma unroll
        for (int h = 0; h < Hc; ++h) {
            float hv = __shfl_sync(0xffffffffu, (h & 1) ? h2.y : h2.x, h >> 1);
            qa = fmaf(hv, Ws[h*Mc + lane], qa);
            ka = fmaf(hv, Ws[Hc*Mc + h*Mc + lane], ka);
            va = fmaf(hv, Ws[2*Hc*Mc + h*Mc + lane], va);
        }
        size_t o = ((size_t)e*BTc + row) * Mc + lane;
        g_Q[o] = qa * LOG2E;
        g_K[o] = ka;
        g_V[o] = va;
    }
}

// ============================================================================
// Kernel 3: flash attention partials. 2 queries/thread (K/V smem loads
// amortized over both), cp.async double-buffered 32-key tiles, split-K=4,
// warp-vote lazy rescale. grid (8 qtiles * 4 ksplits, B, E), block 128.
// ============================================================================
__global__ __launch_bounds__(128)
void k_attn() {
    __shared__ __align__(16) float Ks[2][32*Mc];
    __shared__ __align__(16) float Vs[2][32*Mc];

    int tid = threadIdx.x;
    int bx = blockIdx.x;
    int qtile = bx >> 2, kq = bx & 3;
    int b = blockIdx.y, e = blockIdx.z;
    int eb = e * Bc + b;
    int t0 = qtile * 256 + tid;          // second query is t0 + 128

    // load the two query rows (already log2e-scaled)
    ull qp0[16], qp1[16];
    {
        const ulonglong2* q2 = (const ulonglong2*)(g_Q + ((size_t)eb*Tc + t0) * Mc);
        #pragma unroll
        for (int i = 0; i < 8; i++) { ulonglong2 v = q2[i]; qp0[2*i] = v.x; qp0[2*i+1] = v.y; }
        q2 = (const ulonglong2*)(g_Q + ((size_t)eb*Tc + t0 + 128) * Mc);
        #pragma unroll
        for (int i = 0; i < 8; i++) { ulonglong2 v = q2[i]; qp1[2*i] = v.x; qp1[2*i+1] = v.y; }
    }
    ull op0[16], op1[16];
    #pragma unroll
    for (int i = 0; i < 16; i++) { op0[i] = 0ull; op1[i] = 0ull; }
    float m0 = -1e30f, m1 = -1e30f, l0 = 0.f, l1 = 0.f;

    const float4* Kg = (const float4*)(g_K + ((size_t)eb*Tc + kq*KEYS) * Mc);
    const float4* Vg = (const float4*)(g_V + ((size_t)eb*Tc + kq*KEYS) * Mc);

    // prologue: stage tile 0
    {
        unsigned dK = smem_u32(&Ks[0][0]), dV = smem_u32(&Vs[0][0]);
        cp16(dK + tid*16,        Kg + tid);
        cp16(dK + (tid+128)*16,  Kg + tid + 128);
        cp16(dV + tid*16,        Vg + tid);
        cp16(dV + (tid+128)*16,  Vg + tid + 128);
        cp_commit();
    }

    for (int tile = 0; tile < NT; ++tile) {
        int buf = tile & 1;
        if (tile + 1 < NT) {
            const float4* kp = Kg + (tile+1) * 256;
            const float4* vp = Vg + (tile+1) * 256;
            unsigned dK = smem_u32(&Ks[buf^1][0]), dV = smem_u32(&Vs[buf^1][0]);
            cp16(dK + tid*16,        kp + tid);
            cp16(dK + (tid+128)*16,  kp + tid + 128);
            cp16(dV + tid*16,        vp + tid);
            cp16(dV + (tid+128)*16,  vp + tid + 128);
            cp_commit();
            cp_wait<1>();
        } else {
            cp_wait<0>();
        }
        __syncthreads();

        const ulonglong2* K2 = (const ulonglong2*)Ks[buf];
        const ulonglong2* V2 = (const ulonglong2*)Vs[buf];

        #pragma unroll
        for (int c = 0; c < 4; ++c) {             // 4 chunks of 8 keys
            // ---- S = q . K for 8 keys, both queries share each K load ----
            ull sp0[8], sp1[8];
            #pragma unroll
            for (int j = 0; j < 8; j++) { sp0[j] = 0ull; sp1[j] = 0ull; }
            #pragma unroll
            for (int mp = 0; mp < 8; ++mp) {
                ull qa0 = qp0[2*mp], qb0 = qp0[2*mp+1];
                ull qa1 = qp1[2*mp], qb1 = qp1[2*mp+1];
                #pragma unroll
                for (int j = 0; j < 8; ++j) {
                    ulonglong2 k2 = K2[(c*8 + j)*8 + mp];
                    sp0[j] = fma2(qa0, k2.x, sp0[j]);
                    sp0[j] = fma2(qb0, k2.y, sp0[j]);
                    sp1[j] = fma2(qa1, k2.x, sp1[j]);
                    sp1[j] = fma2(qb1, k2.y, sp1[j]);
                }
            }
            float s0[8], s1[8];
            float c0 = -1e30f, c1 = -1e30f;
            #pragma unroll
            for (int j = 0; j < 8; ++j) {
                float2 f = unpack2(sp0[j]); s0[j] = f.x + f.y; c0 = fmaxf(c0, s0[j]);
                f = unpack2(sp1[j]);        s1[j] = f.x + f.y; c1 = fmaxf(c1, s1[j]);
            }
            // ---- lazy rescale: only when some lane's max increased ----
            bool need = (c0 > m0) | (c1 > m1);
            if (__any_sync(0xffffffffu, need)) {
                float n0 = fmaxf(m0, c0), n1 = fmaxf(m1, c1);
                float sc0 = ex2(m0 - n0), sc1 = ex2(m1 - n1);
                m0 = n0; m1 = n1;
                l0 *= sc0; l1 *= sc1;
                ull s02 = pack2(sc0, sc0), s12 = pack2(sc1, sc1);
                #pragma unroll
                for (int i = 0; i < 16; ++i) {
                    op0[i] = mul2(op0[i], s02);
                    op1[i] = mul2(op1[i], s12);
                }
            }
            // ---- O += p * V, both queries share each V load ----
            #pragma unroll
            for (int j = 0; j < 8; ++j) {
                float p0 = ex2(s0[j] - m0); l0 += p0;
                float p1 = ex2(s1[j] - m1); l1 += p1;
                ull p02 = pack2(p0, p0), p12 = pack2(p1, p1);
                #pragma unroll
                for (int mp = 0; mp < 8; ++mp) {
                    ulonglong2 v2 = V2[(c*8 + j)*8 + mp];
                    op0[2*mp]   = fma2(p02, v2.x, op0[2*mp]);
                    op0[2*mp+1] = fma2(p02, v2.y, op0[2*mp+1]);
                    op1[2*mp]   = fma2(p12, v2.x, op1[2*mp]);
                    op1[2*mp+1] = fma2(p12, v2.y, op1[2*mp+1]);
                }
            }
        }
        __syncthreads();
    }

    // ---- write unnormalized partials ----
    size_t r0 = (size_t)eb*Tc + t0;
    size_t r1 = r0 + 128;
    {
        float4* O = (float4*)(g_pO + ((size_t)kq*EBT + r0) * Mc);
        #pragma unroll
        for (int i = 0; i < 8; ++i) {
            float2 a = unpack2(op0[2*i]), bb = unpack2(op0[2*i+1]);
            O[i] = make_float4(a.x, a.y, bb.x, bb.y);
        }
        O = (float4*)(g_pO + ((size_t)kq*EBT + r1) * Mc);
        #pragma unroll
        for (int i = 0; i < 8; ++i) {
            float2 a = unpack2(op1[2*i]), bb = unpack2(op1[2*i+1]);
            O[i] = make_float4(a.x, a.y, bb.x, bb.y);
        }
        g_pm[kq*EBT + r0] = m0;  g_pl[kq*EBT + r0] = l0;
        g_pm[kq*EBT + r1] = m1;  g_pl[kq*EBT + r1] = l1;
    }
}

// ============================================================================
// Kernel 4: combine split-K partials + cosine epilogue. 1 thread per row.
// ============================================================================
__global__ __launch_bounds__(128)
void k_comb(float* __restrict__ out) {
    int r = blockIdx.x * 128 + threadIdx.x;   // 0 .. EBT-1
    float mv[KQS];
    float m = -1e30f;
    #pragma unroll
    for (int p = 0; p < KQS; ++p) { mv[p] = g_pm[p*EBT + r]; m = fmaxf(m, mv[p]); }
    float l = 0.f;
    float o[Mc];
    #pragma unroll
    for (int i = 0; i < Mc; ++i) o[i] = 0.f;
    #pragma unroll
    for (int p = 0; p < KQS; ++p) {
        float w = ex2(mv[p] - m);
        l = fmaf(w, g_pl[p*EBT + r], l);
        const float4* O4 = (const float4*)(g_pO + ((size_t)p*EBT + r) * Mc);
        #pragma unroll
        for (int i = 0; i < 8; ++i) {
            float4 v = O4[i];
            o[4*i]   = fmaf(w, v.x, o[4*i]);
            o[4*i+1] = fmaf(w, v.y, o[4*i+1]);
            o[4*i+2] = fmaf(w, v.z, o[4*i+2]);
            o[4*i+3] = fmaf(w, v.w, o[4*i+3]);
        }
    }
    float inv_l = 1.0f / l;
    int e = r / BTc;
    int bt = r % BTc;
    float dot = 0.f, no2 = 0.f, nm2 = 0.f;
    const float4* mem4 = (const float4*)(g_mem + (size_t)bt * Mc);
    #pragma unroll
    for (int i = 0; i < 8; ++i) {
        float4 mm = mem4[i];
        float o0 = o[4*i]*inv_l, o1 = o[4*i+1]*inv_l,
              o2 = o[4*i+2]*inv_l, o3 = o[4*i+3]*inv_l;
        dot += mm.x*o0 + mm.y*o1 + mm.z*o2 + mm.w*o3;
        nm2 += mm.x*mm.x + mm.y*mm.y + mm.z*mm.z + mm.w*mm.w;
        no2 += o0*o0 + o1*o1 + o2*o2 + o3*o3;
    }
    float cosv = dot / (fmaxf(sqrtf(nm2), EPSc) * fmaxf(sqrtf(no2), EPSc));
    out[(size_t)bt*Ec + e] = cosv;
}

// ============================================================================
extern "C" void kernel_launch(void* const* d_in, const int* in_sizes, int n_in,
                              void* d_out, int out_size) {
    (void)in_sizes; (void)n_in; (void)out_size;
    const float* x      = (const float*)d_in[0];
    const float* hidden = (const float*)d_in[1];
    const float* memory = (const float*)d_in[2];
    const float* Wq     = (const float*)d_in[3];
    const float* Wk     = (const float*)d_in[4];
    const float* Wv     = (const float*)d_in[5];
    const float* iq     = (const float*)d_in[6];
    float* out = (float*)d_out;

    k_mem<<<BTc/128, 128>>>(x, memory, iq);
    k_qkv<<<dim3(BTc/256, Ec), 256>>>(hidden, Wq, Wk, Wv);
    k_attn<<<dim3(8*KQS, Bc, Ec), 128>>>();
    k_comb<<<EBT/128, 128>>>(out);
}

// round 7
// speedup vs baseline: 1.0236x; 1.0009x over previous
#include <cuda_runtime.h>
#include <cstdint>

typedef unsigned long long ull;

// Problem dims
#define Bc 8
#define Tc 2048
#define Hc 64
#define Mc 32
#define Sc 20
#define Ec 3
#define INc 32
#define BTc (Bc*Tc)          // 16384
#define EBT (Ec*BTc)         // 49152
#define EPSc 1e-8f
#define LOG2E 1.4426950408889634f

// split-K config for attention
#define KQS 4                // key splits
#define KEYS (Tc/KQS)        // 512 keys per block
#define NT (KEYS/32)         // 16 tiles of 32 keys

// Scratch (static __device__ arrays: allocation-free per harness rules)
__device__ float g_Q[Ec*BTc*Mc];     // Q pre-scaled by log2(e)
__device__ float g_K[Ec*BTc*Mc];
__device__ float g_V[Ec*BTc*Mc];
__device__ float g_mem[BTc*Mc];      // memories [B*T, 32]
__device__ float g_pO[KQS*EBT*Mc];   // unnormalized partial O
__device__ float g_pm[KQS*EBT];      // partial running max (log2 domain)
__device__ float g_pl[KQS*EBT];      // partial softmax denom

// ---------- packed f32x2 helpers ----------
__device__ __forceinline__ ull fma2(ull a, ull b, ull c) {
    ull d;
    asm("fma.rn.f32x2 %0, %1, %2, %3;" : "=l"(d) : "l"(a), "l"(b), "l"(c));
    return d;
}
__device__ __forceinline__ ull mul2(ull a, ull b) {
    ull d;
    asm("mul.rn.f32x2 %0, %1, %2;" : "=l"(d) : "l"(a), "l"(b));
    return d;
}
__device__ __forceinline__ ull pack2(float x, float y) {
    ull v;
    asm("mov.b64 %0, {%1, %2};" : "=l"(v) : "f"(x), "f"(y));
    return v;
}
__device__ __forceinline__ float2 unpack2(ull v) {
    float2 f;
    asm("mov.b64 {%0, %1}, %2;" : "=f"(f.x), "=f"(f.y) : "l"(v));
    return f;
}
__device__ __forceinline__ float ex2(float x) {
    float r;
    asm("ex2.approx.f32 %0, %1;" : "=f"(r) : "f"(x));
    return r;
}
// ---------- cp.async helpers ----------
__device__ __forceinline__ unsigned smem_u32(const void* p) {
    return (unsigned)__cvta_generic_to_shared(p);
}
__device__ __forceinline__ void cp16(unsigned dst, const void* src) {
    asm volatile("cp.async.cg.shared.global [%0], [%1], 16;"
                 :: "r"(dst), "l"(src));
}
__device__ __forceinline__ void cp_commit() {
    asm volatile("cp.async.commit_group;");
}
template <int N>
__device__ __forceinline__ void cp_wait() {
    asm volatile("cp.async.wait_group %0;" :: "n"(N));
}

// ============================================================================
// Kernel 1: memories = softmax(x@IQ @ mem^T) @ mem     [B*T, 32]
// One thread per (b,t) row; x streamed (no 32-reg staging -> no spills).
// ============================================================================
__global__ __launch_bounds__(128)
void k_mem(const float* __restrict__ x, const float* __restrict__ memory,
           const float* __restrict__ iq) {
    __shared__ float IQs[INc*Mc];    // 1024
    __shared__ float MEMs[Sc*Mc];    // 640
    int tid = threadIdx.x;
    for (int i = tid; i < INc*Mc; i += 128) IQs[i] = iq[i];
    for (int i = tid; i < Sc*Mc; i += 128) MEMs[i] = memory[i];
    __syncthreads();

    int row = blockIdx.x * 128 + tid;
    const float4* x4 = (const float4*)(x + (size_t)row * INc);

    float q[Mc];
    #pragma unroll
    for (int m = 0; m < Mc; m++) q[m] = 0.f;
    #pragma unroll
    for (int i4 = 0; i4 < 8; i4++) {
        float4 v = x4[i4];
        int i = i4 * 4;
        #pragma unroll
        for (int m = 0; m < Mc; m++) q[m] = fmaf(v.x, IQs[(i+0)*Mc + m], q[m]);
        #pragma unroll
        for (int m = 0; m < Mc; m++) q[m] = fmaf(v.y, IQs[(i+1)*Mc + m], q[m]);
        #pragma unroll
        for (int m = 0; m < Mc; m++) q[m] = fmaf(v.z, IQs[(i+2)*Mc + m], q[m]);
        #pragma unroll
        for (int m = 0; m < Mc; m++) q[m] = fmaf(v.w, IQs[(i+3)*Mc + m], q[m]);
    }
    float lg[Sc];
    #pragma unroll
    for (int s = 0; s < Sc; s++) {
        float acc = 0.f;
        #pragma unroll
        for (int m = 0; m < Mc; m++) acc = fmaf(q[m], MEMs[s*Mc + m], acc);
        lg[s] = acc;
    }
    float mx = lg[0];
    #pragma unroll
    for (int s = 1; s < Sc; s++) mx = fmaxf(mx, lg[s]);
    float sum = 0.f;
    #pragma unroll
    for (int s = 0; s < Sc; s++) {
        lg[s] = ex2((lg[s] - mx) * LOG2E);
        sum += lg[s];
    }
    float inv = 1.0f / sum;
    #pragma unroll
    for (int m = 0; m < Mc; m++) {
        float acc = 0.f;
        #pragma unroll
        for (int s = 0; s < Sc; s++) acc = fmaf(lg[s], MEMs[s*Mc + m], acc);
        g_mem[(size_t)row*Mc + m] = acc * inv;
    }
}

// ============================================================================
// Kernel 2: QKV projections per expert. hidden[E,B*T,64] @ W[e][64,32].
// One warp per 32 rows; lane = output column m. Q pre-scaled by log2(e).
// ============================================================================
__global__ __launch_bounds__(256)
void k_qkv(const float* __restrict__ hidden, const float* __restrict__ Wq,
           const float* __restrict__ Wk, const float* __restrict__ Wv) {
    __shared__ float Ws[3*Hc*Mc];   // 6144 floats
    int e = blockIdx.y;
    int tid = threadIdx.x;
    {
        const float4* wq4 = (const float4*)(Wq + (size_t)e*Hc*Mc);
        const float4* wk4 = (const float4*)(Wk + (size_t)e*Hc*Mc);
        const float4* wv4 = (const float4*)(Wv + (size_t)e*Hc*Mc);
        float4* s0 = (float4*)Ws;
        float4* s1 = (float4*)(Ws + Hc*Mc);
        float4* s2 = (float4*)(Ws + 2*Hc*Mc);
        for (int i = tid; i < Hc*Mc/4; i += 256) {
            s0[i] = wq4[i]; s1[i] = wk4[i]; s2[i] = wv4[i];
        }
    }
    __syncthreads();

    int warp = tid >> 5, lane = tid & 31;
    int rbase = blockIdx.x * 256 + warp * 32;
    for (int i = 0; i < 32; ++i) {
        int row = rbase + i;
        size_t hoff = ((size_t)e*BTc + row) * Hc;
        float2 h2 = ((const float2*)(hidden + hoff))[lane];
        float qa = 0.f, ka = 0.f, va = 0.f;
        #pragma unroll
        for (int h = 0; h < Hc; ++h) {
            float hv = __shfl_sync(0xffffffffu, (h & 1) ? h2.y : h2.x, h >> 1);
            qa = fmaf(hv, Ws[h*Mc + lane], qa);
            ka = fmaf(hv, Ws[Hc*Mc + h*Mc + lane], ka);
            va = fmaf(hv, Ws[2*Hc*Mc + h*Mc + lane], va);
        }
        size_t o = ((size_t)e*BTc + row) * Mc + lane;
        g_Q[o] = qa * LOG2E;
        g_K[o] = ka;
        g_V[o] = va;
    }
}

// ============================================================================
// Kernel 3: flash attention partials. 2 queries/thread (K/V smem loads
// amortized over both), cp.async double-buffered 32-key tiles, split-K=4,
// warp-vote lazy rescale. grid (8 qtiles * 4 ksplits, B, E), block 128.
// ============================================================================
__global__ __launch_bounds__(128)
void k_attn() {
    __shared__ __align__(16) float Ks[2][32*Mc];
    __shared__ __align__(16) float Vs[2][32*Mc];

    int tid = threadIdx.x;
    int bx = blockIdx.x;
    int qtile = bx >> 2, kq = bx & 3;
    int b = blockIdx.y, e = blockIdx.z;
    int eb = e * Bc + b;
    int t0 = qtile * 256 + tid;          // second query is t0 + 128

    // load the two query rows (already log2e-scaled)
    ull qp0[16], qp1[16];
    {
        const ulonglong2* q2 = (const ulonglong2*)(g_Q + ((size_t)eb*Tc + t0) * Mc);
        #pragma unroll
        for (int i = 0; i < 8; i++) { ulonglong2 v = q2[i]; qp0[2*i] = v.x; qp0[2*i+1] = v.y; }
        q2 = (const ulonglong2*)(g_Q + ((size_t)eb*Tc + t0 + 128) * Mc);
        #pragma unroll
        for (int i = 0; i < 8; i++) { ulonglong2 v = q2[i]; qp1[2*i] = v.x; qp1[2*i+1] = v.y; }
    }
    ull op0[16], op1[16];
    #pragma unroll
    for (int i = 0; i < 16; i++) { op0[i] = 0ull; op1[i] = 0ull; }
    float m0 = -1e30f, m1 = -1e30f, l0 = 0.f, l1 = 0.f;

    const float4* Kg = (const float4*)(g_K + ((size_t)eb*Tc + kq*KEYS) * Mc);
    const float4* Vg = (const float4*)(g_V + ((size_t)eb*Tc + kq*KEYS) * Mc);

    // prologue: stage tile 0
    {
        unsigned dK = smem_u32(&Ks[0][0]), dV = smem_u32(&Vs[0][0]);
        cp16(dK + tid*16,        Kg + tid);
        cp16(dK + (tid+128)*16,  Kg + tid + 128);
        cp16(dV + tid*16,        Vg + tid);
        cp16(dV + (tid+128)*16,  Vg + tid + 128);
        cp_commit();
    }

    for (int tile = 0; tile < NT; ++tile) {
        int buf = tile & 1;
        if (tile + 1 < NT) {
            const float4* kp = Kg + (tile+1) * 256;
            const float4* vp = Vg + (tile+1) * 256;
            unsigned dK = smem_u32(&Ks[buf^1][0]), dV = smem_u32(&Vs[buf^1][0]);
            cp16(dK + tid*16,        kp + tid);
            cp16(dK + (tid+128)*16,  kp + tid + 128);
            cp16(dV + tid*16,        vp + tid);
            cp16(dV + (tid+128)*16,  vp + tid + 128);
            cp_commit();
            cp_wait<1>();
        } else {
            cp_wait<0>();
        }
        __syncthreads();

        const ulonglong2* K2 = (const ulonglong2*)Ks[buf];
        const ulonglong2* V2 = (const ulonglong2*)Vs[buf];

        #pragma unroll
        for (int c = 0; c < 4; ++c) {             // 4 chunks of 8 keys
            // ---- S = q . K for 8 keys, both queries share each K load ----
            ull sp0[8], sp1[8];
            #pragma unroll
            for (int j = 0; j < 8; j++) { sp0[j] = 0ull; sp1[j] = 0ull; }
            #pragma unroll
            for (int mp = 0; mp < 8; ++mp) {
                ull qa0 = qp0[2*mp], qb0 = qp0[2*mp+1];
                ull qa1 = qp1[2*mp], qb1 = qp1[2*mp+1];
                #pragma unroll
                for (int j = 0; j < 8; ++j) {
                    ulonglong2 k2 = K2[(c*8 + j)*8 + mp];
                    sp0[j] = fma2(qa0, k2.x, sp0[j]);
                    sp0[j] = fma2(qb0, k2.y, sp0[j]);
                    sp1[j] = fma2(qa1, k2.x, sp1[j]);
                    sp1[j] = fma2(qb1, k2.y, sp1[j]);
                }
            }
            float s0[8], s1[8];
            float c0 = -1e30f, c1 = -1e30f;
            #pragma unroll
            for (int j = 0; j < 8; ++j) {
                float2 f = unpack2(sp0[j]); s0[j] = f.x + f.y; c0 = fmaxf(c0, s0[j]);
                f = unpack2(sp1[j]);        s1[j] = f.x + f.y; c1 = fmaxf(c1, s1[j]);
            }
            // ---- lazy rescale: only when some lane's max increased ----
            bool need = (c0 > m0) | (c1 > m1);
            if (__any_sync(0xffffffffu, need)) {
                float n0 = fmaxf(m0, c0), n1 = fmaxf(m1, c1);
                float sc0 = ex2(m0 - n0), sc1 = ex2(m1 - n1);
                m0 = n0; m1 = n1;
                l0 *= sc0; l1 *= sc1;
                ull s02 = pack2(sc0, sc0), s12 = pack2(sc1, sc1);
                #pragma unroll
                for (int i = 0; i < 16; ++i) {
                    op0[i] = mul2(op0[i], s02);
                    op1[i] = mul2(op1[i], s12);
                }
            }
            // ---- O += p * V, both queries share each V load ----
            #pragma unroll
            for (int j = 0; j < 8; ++j) {
                float p0 = ex2(s0[j] - m0); l0 += p0;
                float p1 = ex2(s1[j] - m1); l1 += p1;
                ull p02 = pack2(p0, p0), p12 = pack2(p1, p1);
                #pragma unroll
                for (int mp = 0; mp < 8; ++mp) {
                    ulonglong2 v2 = V2[(c*8 + j)*8 + mp];
                    op0[2*mp]   = fma2(p02, v2.x, op0[2*mp]);
                    op0[2*mp+1] = fma2(p02, v2.y, op0[2*mp+1]);
                    op1[2*mp]   = fma2(p12, v2.x, op1[2*mp]);
                    op1[2*mp+1] = fma2(p12, v2.y, op1[2*mp+1]);
                }
            }
        }
        __syncthreads();
    }

    // ---- write unnormalized partials ----
    size_t r0 = (size_t)eb*Tc + t0;
    size_t r1 = r0 + 128;
    {
        float4* O = (float4*)(g_pO + ((size_t)kq*EBT + r0) * Mc);
        #pragma unroll
        for (int i = 0; i < 8; ++i) {
            float2 a = unpack2(op0[2*i]), bb = unpack2(op0[2*i+1]);
            O[i] = make_float4(a.x, a.y, bb.x, bb.y);
        }
        O = (float4*)(g_pO + ((size_t)kq*EBT + r1) * Mc);
        #pragma unroll
        for (int i = 0; i < 8; ++i) {
            float2 a = unpack2(op1[2*i]), bb = unpack2(op1[2*i+1]);
            O[i] = make_float4(a.x, a.y, bb.x, bb.y);
        }
        g_pm[kq*EBT + r0] = m0;  g_pl[kq*EBT + r0] = l0;
        g_pm[kq*EBT + r1] = m1;  g_pl[kq*EBT + r1] = l1;
    }
}

// ============================================================================
// Kernel 4: combine split-K partials + cosine epilogue. 1 thread per row.
// ============================================================================
__global__ __launch_bounds__(128)
void k_comb(float* __restrict__ out) {
    int r = blockIdx.x * 128 + threadIdx.x;   // 0 .. EBT-1
    float mv[KQS];
    float m = -1e30f;
    #pragma unroll
    for (int p = 0; p < KQS; ++p) { mv[p] = g_pm[p*EBT + r]; m = fmaxf(m, mv[p]); }
    float l = 0.f;
    float o[Mc];
    #pragma unroll
    for (int i = 0; i < Mc; ++i) o[i] = 0.f;
    #pragma unroll
    for (int p = 0; p < KQS; ++p) {
        float w = ex2(mv[p] - m);
        l = fmaf(w, g_pl[p*EBT + r], l);
        const float4* O4 = (const float4*)(g_pO + ((size_t)p*EBT + r) * Mc);
        #pragma unroll
        for (int i = 0; i < 8; ++i) {
            float4 v = O4[i];
            o[4*i]   = fmaf(w, v.x, o[4*i]);
            o[4*i+1] = fmaf(w, v.y, o[4*i+1]);
            o[4*i+2] = fmaf(w, v.z, o[4*i+2]);
            o[4*i+3] = fmaf(w, v.w, o[4*i+3]);
        }
    }
    float inv_l = 1.0f / l;
    int e = r / BTc;
    int bt = r % BTc;
    float dot = 0.f, no2 = 0.f, nm2 = 0.f;
    const float4* mem4 = (const float4*)(g_mem + (size_t)bt * Mc);
    #pragma unroll
    for (int i = 0; i < 8; ++i) {
        float4 mm = mem4[i];
        float o0 = o[4*i]*inv_l, o1 = o[4*i+1]*inv_l,
              o2 = o[4*i+2]*inv_l, o3 = o[4*i+3]*inv_l;
        dot += mm.x*o0 + mm.y*o1 + mm.z*o2 + mm.w*o3;
        nm2 += mm.x*mm.x + mm.y*mm.y + mm.z*mm.z + mm.w*mm.w;
        no2 += o0*o0 + o1*o1 + o2*o2 + o3*o3;
    }
    float cosv = dot / (fmaxf(sqrtf(nm2), EPSc) * fmaxf(sqrtf(no2), EPSc));
    out[(size_t)bt*Ec + e] = cosv;
}

// ============================================================================
extern "C" void kernel_launch(void* const* d_in, const int* in_sizes, int n_in,
                              void* d_out, int out_size) {
    (void)in_sizes; (void)n_in; (void)out_size;
    const float* x      = (const float*)d_in[0];
    const float* hidden = (const float*)d_in[1];
    const float* memory = (const float*)d_in[2];
    const float* Wq     = (const float*)d_in[3];
    const float* Wk     = (const float*)d_in[4];
    const float* Wv     = (const float*)d_in[5];
    const float* iq     = (const float*)d_in[6];
    float* out = (float*)d_out;

    k_mem<<<BTc/128, 128>>>(x, memory, iq);
    k_qkv<<<dim3(BTc/256, Ec), 256>>>(hidden, Wq, Wk, Wv);
    k_attn<<<dim3(8*KQS, Bc, Ec), 128>>>();
    k_comb<<<EBT/128, 128>>>(out);
}

// round 12
// speedup vs baseline: 2.4261x; 2.3703x over previous
#include <cuda_runtime.h>
#include <cuda_bf16.h>
#include <cstdint>

// Problem dims
#define Bc 8
#define Tc 2048
#define Hc 64
#define Mc 32
#define Sc 20
#define Ec 3
#define INc 32
#define BTc (Bc*Tc)          // 16384
#define EBc (Ec*Bc)          // 24
#define EPSc 1e-8f
#define LOG2E 1.4426950408889634f

// attention tiling
#define NK 64                // keys per chunk
#define NCH (Tc/NK)          // 32 chunks
#define QTILES (Tc/128)      // 16

// Scratch (static __device__ arrays: allocation-free per harness rules)
__device__ __align__(16) __nv_bfloat16 g_Qb[EBc*Tc*64];   // [eb][t][qh 0-31 | ql 32-63], log2e-scaled
__device__ __align__(16) __nv_bfloat16 g_Kb[EBc*Tc*64];   // [eb][t][kh 0-31 | kl 32-63]
__device__ __align__(16) __nv_bfloat16 g_Vt[EBc*NCH*64*64]; // per chunk: V^T [m: vh 0-31|vl 32-63][key 0-63]
__device__ float g_mem[BTc*Mc];                            // memories [B*T, 32]

// ---------- helpers ----------
__device__ __forceinline__ float ex2(float x) {
    float r; asm("ex2.approx.f32 %0, %1;" : "=f"(r) : "f"(x)); return r;
}
__device__ __forceinline__ uint32_t smem_u32(const void* p) {
    return (uint32_t)__cvta_generic_to_shared(p);
}
__device__ __forceinline__ void cp16(uint32_t dst, const void* src) {
    asm volatile("cp.async.cg.shared.global [%0], [%1], 16;" :: "r"(dst), "l"(src));
}
__device__ __forceinline__ void cp_commit() { asm volatile("cp.async.commit_group;"); }
template <int N> __device__ __forceinline__ void cp_wait() {
    asm volatile("cp.async.wait_group %0;" :: "n"(N));
}
// bf16x2 pack: result = {hi16 = cvt(a), lo16 = cvt(b)}
__device__ __forceinline__ uint32_t cvt2(float hi, float lo) {
    uint32_t r;
    asm("cvt.rn.bf16x2.f32 %0, %1, %2;" : "=r"(r) : "f"(hi), "f"(lo));
    return r;
}
// HMMA m16n8k16 row.col f32.bf16.bf16.f32
__device__ __forceinline__ void mma16816(float* c, const uint32_t* a, uint32_t b0, uint32_t b1) {
    asm volatile("mma.sync.aligned.m16n8k16.row.col.f32.bf16.bf16.f32 "
        "{%0,%1,%2,%3}, {%4,%5,%6,%7}, {%8,%9}, {%0,%1,%2,%3};"
        : "+f"(c[0]), "+f"(c[1]), "+f"(c[2]), "+f"(c[3])
        : "r"(a[0]), "r"(a[1]), "r"(a[2]), "r"(a[3]), "r"(b0), "r"(b1));
}

// ============================================================================
// Kernel 1: memories = softmax(x@IQ @ mem^T) @ mem     [B*T, 32]
// ============================================================================
__global__ __launch_bounds__(128)
void k_mem(const float* __restrict__ x, const float* __restrict__ memory,
           const float* __restrict__ iq) {
    __shared__ float IQs[INc*Mc];
    __shared__ float MEMs[Sc*Mc];
    int tid = threadIdx.x;
    for (int i = tid; i < INc*Mc; i += 128) IQs[i] = iq[i];
    for (int i = tid; i < Sc*Mc; i += 128) MEMs[i] = memory[i];
    __syncthreads();

    int row = blockIdx.x * 128 + tid;
    const float4* x4 = (const float4*)(x + (size_t)row * INc);
    float q[Mc];
    #pragma unroll
    for (int m = 0; m < Mc; m++) q[m] = 0.f;
    #pragma unroll
    for (int i4 = 0; i4 < 8; i4++) {
        float4 v = x4[i4];
        int i = i4 * 4;
        #pragma unroll
        for (int m = 0; m < Mc; m++) q[m] = fmaf(v.x, IQs[(i+0)*Mc + m], q[m]);
        #pragma unroll
        for (int m = 0; m < Mc; m++) q[m] = fmaf(v.y, IQs[(i+1)*Mc + m], q[m]);
        #pragma unroll
        for (int m = 0; m < Mc; m++) q[m] = fmaf(v.z, IQs[(i+2)*Mc + m], q[m]);
        #pragma unroll
        for (int m = 0; m < Mc; m++) q[m] = fmaf(v.w, IQs[(i+3)*Mc + m], q[m]);
    }
    float lg[Sc];
    #pragma unroll
    for (int s = 0; s < Sc; s++) {
        float acc = 0.f;
        #pragma unroll
        for (int m = 0; m < Mc; m++) acc = fmaf(q[m], MEMs[s*Mc + m], acc);
        lg[s] = acc;
    }
    float mx = lg[0];
    #pragma unroll
    for (int s = 1; s < Sc; s++) mx = fmaxf(mx, lg[s]);
    float sum = 0.f;
    #pragma unroll
    for (int s = 0; s < Sc; s++) { lg[s] = ex2((lg[s] - mx) * LOG2E); sum += lg[s]; }
    float inv = 1.0f / sum;
    #pragma unroll
    for (int m = 0; m < Mc; m++) {
        float acc = 0.f;
        #pragma unroll
        for (int s = 0; s < Sc; s++) acc = fmaf(lg[s], MEMs[s*Mc + m], acc);
        g_mem[(size_t)row*Mc + m] = acc * inv;
    }
}

// ============================================================================
// Kernel 2: QKV projections -> bf16 hi/lo, dense MMA-ready tiles.
// ============================================================================
__global__ __launch_bounds__(256)
void k_qkv(const float* __restrict__ hidden, const float* __restrict__ Wq,
           const float* __restrict__ Wk, const float* __restrict__ Wv) {
    __shared__ float Ws[3*Hc*Mc];
    int e = blockIdx.y;
    int tid = threadIdx.x;
    {
        const float4* wq4 = (const float4*)(Wq + (size_t)e*Hc*Mc);
        const float4* wk4 = (const float4*)(Wk + (size_t)e*Hc*Mc);
        const float4* wv4 = (const float4*)(Wv + (size_t)e*Hc*Mc);
        float4* s0 = (float4*)Ws;
        float4* s1 = (float4*)(Ws + Hc*Mc);
        float4* s2 = (float4*)(Ws + 2*Hc*Mc);
        for (int i = tid; i < Hc*Mc/4; i += 256) { s0[i] = wq4[i]; s1[i] = wk4[i]; s2[i] = wv4[i]; }
    }
    __syncthreads();

    int warp = tid >> 5, lane = tid & 31;
    int rbase = blockIdx.x * 256 + warp * 32;
    unsigned short vh_p = 0, vl_p = 0;
    for (int i = 0; i < 32; ++i) {
        int row = rbase + i;
        size_t hoff = ((size_t)e*BTc + row) * Hc;
        float2 h2 = ((const float2*)(hidden + hoff))[lane];
        float qa = 0.f, ka = 0.f, va = 0.f;
        #pragma unroll
        for (int h = 0; h < Hc; ++h) {
            float hv = __shfl_sync(0xffffffffu, (h & 1) ? h2.y : h2.x, h >> 1);
            qa = fmaf(hv, Ws[h*Mc + lane], qa);
            ka = fmaf(hv, Ws[Hc*Mc + h*Mc + lane], ka);
            va = fmaf(hv, Ws[2*Hc*Mc + h*Mc + lane], va);
        }
        qa *= LOG2E;
        __nv_bfloat16 qh = __float2bfloat16(qa);
        __nv_bfloat16 qlo = __float2bfloat16(qa - __bfloat162float(qh));
        __nv_bfloat16 kh = __float2bfloat16(ka);
        __nv_bfloat16 klo = __float2bfloat16(ka - __bfloat162float(kh));
        __nv_bfloat16 vh = __float2bfloat16(va);
        __nv_bfloat16 vlo = __float2bfloat16(va - __bfloat162float(vh));

        int bb = row >> 11, tt = row & 2047;
        int eb = e * Bc + bb;
        size_t qko = ((size_t)eb*Tc + tt) * 64;
        g_Qb[qko + lane]      = qh;
        g_Qb[qko + lane + 32] = qlo;
        g_Kb[qko + lane]      = kh;
        g_Kb[qko + lane + 32] = klo;
        // V^T tile: [m 0-63][key 0-63], pair-packed 4B stores every 2 keys
        if (i & 1) {
            int tile = eb*NCH + (tt >> 6);
            int rk = tt & 63;
            __nv_bfloat16* Vt = g_Vt + (size_t)tile * 4096;
            uint32_t phv = ((uint32_t)__bfloat16_as_ushort(vh)  << 16) | vh_p;
            uint32_t plv = ((uint32_t)__bfloat16_as_ushort(vlo) << 16) | vl_p;
            *(uint32_t*)(Vt + lane*64 + (rk-1))        = phv;
            *(uint32_t*)(Vt + (lane+32)*64 + (rk-1))   = plv;
        } else {
            vh_p = __bfloat16_as_ushort(vh); vl_p = __bfloat16_as_ushort(vlo);
        }
    }
}

// ============================================================================
// Kernel 3: HMMA flash attention + fused cosine epilogue.
// CTA = 128 queries (4 warps x 32q), all 2048 keys in 32 chunks of 64.
// bf16 hi/lo emulation: QK = QhKh+QhKl+QlKh; PV = PhVh+PlVh+PhVl.
// Cosine is scale-invariant => no softmax denominator needed.
// ============================================================================
__global__ __launch_bounds__(128)
void k_attn(float* __restrict__ out) {
    // padded rows: 64 cols bf16 = 32 words + 4 pad = 36 words (144B) -> conflict-free
    __shared__ __align__(16) uint32_t sK[2][64*36];
    __shared__ __align__(16) uint32_t sV[2][64*36];

    int tid = threadIdx.x, warp = tid >> 5, lane = tid & 31;
    int qi = lane >> 2, t4 = lane & 3;
    int qtile = blockIdx.x, b = blockIdx.y, e = blockIdx.z;
    int eb = e * Bc + b;

    const char* Kg = (const char*)g_Kb + (size_t)(eb*Tc) * 128;
    const char* Vg = (const char*)g_Vt + (size_t)(eb*NCH) * 8192;

    // ---- load Q fragments (held in registers whole kernel) ----
    // aQ[mt][f], f: 0=Qh ks0, 1=Qh ks1, 2=Ql ks0, 3=Ql ks1 ; each 4 regs
    uint32_t aQ[2][4][4];
    {
        const char* Qg = (const char*)g_Qb + ((size_t)eb*Tc + qtile*128) * 128;
        #pragma unroll
        for (int mt = 0; mt < 2; ++mt) {
            int r = warp*32 + mt*16 + qi;
            #pragma unroll
            for (int f = 0; f < 4; ++f) {
                int cb = (f >> 1)*32 + (f & 1)*16 + 2*t4;  // byte col base /2
                aQ[mt][f][0] = *(const uint32_t*)(Qg + (size_t)r*128     + cb*2);
                aQ[mt][f][1] = *(const uint32_t*)(Qg + (size_t)(r+8)*128 + cb*2);
                aQ[mt][f][2] = *(const uint32_t*)(Qg + (size_t)r*128     + cb*2 + 16);
                aQ[mt][f][3] = *(const uint32_t*)(Qg + (size_t)(r+8)*128 + cb*2 + 16);
            }
        }
    }

    // ---- prologue: stage chunk 0 ----
    {
        uint32_t dK = smem_u32(&sK[0][0]), dV = smem_u32(&sV[0][0]);
        #pragma unroll
        for (int i = 0; i < 4; ++i) {
            int seg = tid + i*128;
            uint32_t doff = (seg >> 3)*144 + (seg & 7)*16;
            cp16(dK + doff, Kg + seg*16);
            cp16(dV + doff, Vg + seg*16);
        }
        cp_commit();
    }

    float oc[2][4][4];
    #pragma unroll
    for (int mt = 0; mt < 2; ++mt)
        #pragma unroll
        for (int nt = 0; nt < 4; ++nt)
            #pragma unroll
            for (int j = 0; j < 4; ++j) oc[mt][nt][j] = 0.f;
    float mrow[2][2] = {{-1e30f,-1e30f},{-1e30f,-1e30f}};

    for (int c = 0; c < NCH; ++c) {
        int buf = c & 1;
        if (c + 1 < NCH) {
            uint32_t dK = smem_u32(&sK[buf^1][0]), dV = smem_u32(&sV[buf^1][0]);
            const char* kp = Kg + (size_t)(c+1)*8192;
            const char* vp = Vg + (size_t)(c+1)*8192;
            #pragma unroll
            for (int i = 0; i < 4; ++i) {
                int seg = tid + i*128;
                uint32_t doff = (seg >> 3)*144 + (seg & 7)*16;
                cp16(dK + doff, kp + seg*16);
                cp16(dV + doff, vp + seg*16);
            }
            cp_commit();
            cp_wait<1>();
        } else {
            cp_wait<0>();
        }
        __syncthreads();

        const uint32_t* Kb = sK[buf];
        const uint32_t* Vb = sV[buf];

        // ---- S = Qh.Kh + Qh.Kl + Ql.Kh  (fp32 frags) ----
        float s[2][8][4];
        #pragma unroll
        for (int nt = 0; nt < 8; ++nt) {
            uint32_t base = (uint32_t)(nt*8 + qi)*36 + t4;
            uint32_t bh0a = Kb[base],    bh0b = Kb[base+4];
            uint32_t bh1a = Kb[base+8],  bh1b = Kb[base+12];
            uint32_t bl0a = Kb[base+16], bl0b = Kb[base+20];
            uint32_t bl1a = Kb[base+24], bl1b = Kb[base+28];
            #pragma unroll
            for (int mt = 0; mt < 2; ++mt) {
                float* cc = s[mt][nt];
                cc[0]=0.f; cc[1]=0.f; cc[2]=0.f; cc[3]=0.f;
                mma16816(cc, aQ[mt][0], bh0a, bh0b);
                mma16816(cc, aQ[mt][1], bh1a, bh1b);
                mma16816(cc, aQ[mt][0], bl0a, bl0b);
                mma16816(cc, aQ[mt][1], bl1a, bl1b);
                mma16816(cc, aQ[mt][2], bh0a, bh0b);
                mma16816(cc, aQ[mt][3], bh1a, bh1b);
            }
        }

        // ---- online max update (per row; quad = 4 lanes share a row) ----
        float mn[2][2], sc[2][2];
        #pragma unroll
        for (int mt = 0; mt < 2; ++mt) {
            float c0 = -1e30f, c1 = -1e30f;
            #pragma unroll
            for (int nt = 0; nt < 8; ++nt) {
                c0 = fmaxf(c0, fmaxf(s[mt][nt][0], s[mt][nt][1]));
                c1 = fmaxf(c1, fmaxf(s[mt][nt][2], s[mt][nt][3]));
            }
            c0 = fmaxf(c0, __shfl_xor_sync(0xffffffffu, c0, 1));
            c0 = fmaxf(c0, __shfl_xor_sync(0xffffffffu, c0, 2));
            c1 = fmaxf(c1, __shfl_xor_sync(0xffffffffu, c1, 1));
            c1 = fmaxf(c1, __shfl_xor_sync(0xffffffffu, c1, 2));
            mn[mt][0] = fmaxf(mrow[mt][0], c0);
            mn[mt][1] = fmaxf(mrow[mt][1], c1);
            sc[mt][0] = ex2(mrow[mt][0] - mn[mt][0]);
            sc[mt][1] = ex2(mrow[mt][1] - mn[mt][1]);
            mrow[mt][0] = mn[mt][0];
            mrow[mt][1] = mn[mt][1];
            #pragma unroll
            for (int nt = 0; nt < 4; ++nt) {
                oc[mt][nt][0] *= sc[mt][0]; oc[mt][nt][1] *= sc[mt][0];
                oc[mt][nt][2] *= sc[mt][1]; oc[mt][nt][3] *= sc[mt][1];
            }
        }

        // ---- P (bf16 hi/lo A-frags straight from S frags) + PV ----
        #pragma unroll
        for (int ks = 0; ks < 4; ++ks) {
            uint32_t aph[2][4], apl[2][4];
            #pragma unroll
            for (int mt = 0; mt < 2; ++mt) {
                float* sa = s[mt][2*ks];
                float* sb = s[mt][2*ks+1];
                float p00 = ex2(sa[0]-mn[mt][0]), p01 = ex2(sa[1]-mn[mt][0]);
                float p10 = ex2(sa[2]-mn[mt][1]), p11 = ex2(sa[3]-mn[mt][1]);
                float p20 = ex2(sb[0]-mn[mt][0]), p21 = ex2(sb[1]-mn[mt][0]);
                float p30 = ex2(sb[2]-mn[mt][1]), p31 = ex2(sb[3]-mn[mt][1]);
                uint32_t h0 = cvt2(p01, p00), h1 = cvt2(p11, p10);
                uint32_t h2 = cvt2(p21, p20), h3 = cvt2(p31, p30);
                aph[mt][0] = h0; aph[mt][1] = h1; aph[mt][2] = h2; aph[mt][3] = h3;
                apl[mt][0] = cvt2(p01 - __uint_as_float(h0 & 0xffff0000u),
                                  p00 - __uint_as_float(h0 << 16));
                apl[mt][1] = cvt2(p11 - __uint_as_float(h1 & 0xffff0000u),
                                  p10 - __uint_as_float(h1 << 16));
                apl[mt][2] = cvt2(p21 - __uint_as_float(h2 & 0xffff0000u),
                                  p20 - __uint_as_float(h2 << 16));
                apl[mt][3] = cvt2(p31 - __uint_as_float(h3 & 0xffff0000u),
                                  p30 - __uint_as_float(h3 << 16));
            }
            #pragma unroll
            for (int nt = 0; nt < 4; ++nt) {
                uint32_t base = (uint32_t)(nt*8 + qi)*36 + ks*8 + t4;
                uint32_t bh0 = Vb[base],          bh1 = Vb[base+4];
                uint32_t bl0 = Vb[base + 32*36],  bl1 = Vb[base + 32*36 + 4];
                #pragma unroll
                for (int mt = 0; mt < 2; ++mt) {
                    mma16816(oc[mt][nt], aph[mt], bh0, bh1);
                    mma16816(oc[mt][nt], apl[mt], bh0, bh1);
                    mma16816(oc[mt][nt], aph[mt], bl0, bl1);
                }
            }
        }
        __syncthreads();
    }

    // ---- cosine epilogue (scale-invariant: no softmax denominator) ----
    #pragma unroll
    for (int mt = 0; mt < 2; ++mt) {
        int t_row = qtile*128 + warp*32 + mt*16 + qi;
        int bt0 = b*Tc + t_row;
        int bt1 = bt0 + 8;
        float d0 = 0.f, n0 = 0.f, g0 = 0.f;
        float d1 = 0.f, n1 = 0.f, g1 = 0.f;
        #pragma unroll
        for (int nt = 0; nt < 4; ++nt) {
            int col = nt*8 + 2*t4;
            float2 m0 = *(const float2*)(g_mem + (size_t)bt0*Mc + col);
            float2 m1 = *(const float2*)(g_mem + (size_t)bt1*Mc + col);
            float o00 = oc[mt][nt][0], o01 = oc[mt][nt][1];
            float o10 = oc[mt][nt][2], o11 = oc[mt][nt][3];
            d0 += m0.x*o00 + m0.y*o01;  n0 += o00*o00 + o01*o01;  g0 += m0.x*m0.x + m0.y*m0.y;
            d1 += m1.x*o10 + m1.y*o11;  n1 += o10*o10 + o11*o11;  g1 += m1.x*m1.x + m1.y*m1.y;
        }
        #pragma unroll
        for (int w = 1; w <= 2; w <<= 1) {
            d0 += __shfl_xor_sync(0xffffffffu, d0, w);
            n0 += __shfl_xor_sync(0xffffffffu, n0, w);
            g0 += __shfl_xor_sync(0xffffffffu, g0, w);
            d1 += __shfl_xor_sync(0xffffffffu, d1, w);
            n1 += __shfl_xor_sync(0xffffffffu, n1, w);
            g1 += __shfl_xor_sync(0xffffffffu, g1, w);
        }
        if (t4 == 0) {
            float c0 = d0 / (fmaxf(sqrtf(g0), EPSc) * fmaxf(sqrtf(n0), EPSc));
            float c1 = d1 / (fmaxf(sqrtf(g1), EPSc) * fmaxf(sqrtf(n1), EPSc));
            out[(size_t)bt0*Ec + e] = c0;
            out[(size_t)bt1*Ec + e] = c1;
        }
    }
}

// ============================================================================
extern "C" void kernel_launch(void* const* d_in, const int* in_sizes, int n_in,
                              void* d_out, int out_size) {
    (void)in_sizes; (void)n_in; (void)out_size;
    const float* x      = (const float*)d_in[0];
    const float* hidden = (const float*)d_in[1];
    const float* memory = (const float*)d_in[2];
    const float* Wq     = (const float*)d_in[3];
    const float* Wk     = (const float*)d_in[4];
    const float* Wv     = (const float*)d_in[5];
    const float* iq     = (const float*)d_in[6];
    float* out = (float*)d_out;

    k_mem<<<BTc/128, 128>>>(x, memory, iq);
    k_qkv<<<dim3(BTc/256, Ec), 256>>>(hidden, Wq, Wk, Wv);
    k_attn<<<dim3(QTILES, Bc, Ec), 128>>>(out);
}